// round 11
// baseline (speedup 1.0000x reference)
#include <cuda_runtime.h>
#include <cuda_bf16.h>
#include <math.h>

// Problem constants
#define BB   4
#define SS   2048
#define DD   1024
#define HH   16
#define DH   64
#define KTOP 409        // max(S // 5, 1)

// ---------------- scratch (device globals; no allocation allowed) ----------------
__device__ float   g_Qt[(size_t)BB * DD * SS];   // Q transposed: [b*D + j][s]
__device__ float   g_Kt[(size_t)BB * DD * SS];   // K transposed
__device__ float2  g_P[(size_t)BB * DD * SS];    // per-(b,h,d) spectrum product Q*conj(K)
__device__ float   g_att[BB * DD];               // attended, flattened heads
__device__ float   g_y[BB * DD];                 // final per-batch output row
__device__ float2  g_twf[1024];                  // FFT twiddles exp(-2*pi*i*j/2048)

// ---------------- helpers ----------------
// In-place radix-2 DIT FFT of 2048 complex floats in shared memory.
// Input must be pre-bit-reversed. 256 threads. Caller syncs before the call.
__device__ void fft2048f(float2* z, const float2* tw) {
    int tid = threadIdx.x;
    for (int half = 1; half < 2048; half <<= 1) {
        int step = 1024 / half;  // twiddle stride
        for (int jj = tid; jj < 1024; jj += 256) {
            int p  = jj & (half - 1);
            int i0 = ((jj ^ p) << 1) | p;  // (jj - p)*2 + p
            int i1 = i0 + half;
            float2 w = tw[p * step];
            float2 v = z[i1];
            float tr = w.x * v.x - w.y * v.y;
            float ti = w.x * v.y + w.y * v.x;
            float2 u = z[i0];
            z[i0] = make_float2(u.x + tr, u.y + ti);
            z[i1] = make_float2(u.x - tr, u.y - ti);
        }
        __syncthreads();
    }
}

// Order-preserving float <-> uint encode (ascending uint order == ascending float order)
__device__ __forceinline__ unsigned int fenc(float v) {
    unsigned int u = __float_as_uint(v);
    return (u & 0x80000000u) ? ~u : (u | 0x80000000u);
}
__device__ __forceinline__ float fdec(unsigned int e) {
    unsigned int u = (e & 0x80000000u) ? (e & 0x7FFFFFFFu) : ~e;
    return __uint_as_float(u);
}

// ---------------- kernel 0: twiddle table ----------------
__global__ void tw_init_kernel() {
    int i = blockIdx.x * blockDim.x + threadIdx.x;
    if (i < 1024) {
        double ang = -2.0 * 3.14159265358979323846 * (double)i / 2048.0;
        g_twf[i] = make_float2((float)cos(ang), (float)sin(ang));
    }
}

// ---------------- kernel 1: SGEMM, transposed output, f32x2 packed FMA ----------------
// Ct[(b*D + j)*S + s] = sum_c X[(b*S+s)*D + c] * W[c*D + j] + bias[j]
#define BM 128
#define BN 128
#define BK 16
__global__ __launch_bounds__(256, 2)
void sgemm_tn_kernel(const float* __restrict__ X, const float* __restrict__ W,
                     const float* __restrict__ bias, int which) {
    float* Ct = which ? g_Kt : g_Qt;
    int b  = blockIdx.z;
    int j0 = blockIdx.x * BM;
    int s0 = blockIdx.y * BN;
    const float* Xb = X + (size_t)b * SS * DD;

    __shared__ __align__(16) float As[2][BK][BM];  // As[.][k][m] = W[(kt+k)*D + j0+m]
    __shared__ __align__(16) float Bs[2][BK][BN];  // Bs[.][k][n] = Xb[(s0+n)*D + kt+k]

    int tid = threadIdx.x;
    int tx = tid & 15, ty = tid >> 4;
    int m0 = tx * 8, n0 = ty * 8;

    // loader indices: two float4 loads each for A and B per thread
    int kA = tid >> 4;                 // same for both A loads
    int mA0 = (tid * 2) & 31;
    int mA1 = mA0 + 1;
    int nB = tid >> 1;                 // same for both B loads
    int kB0 = (tid * 2) & 3;
    int kB1 = kB0 + 1;

    unsigned long long acc2[8][4];     // packed f32x2 accumulators (m, n-pairs)
#pragma unroll
    for (int i = 0; i < 8; i++)
#pragma unroll
        for (int j = 0; j < 4; j++) acc2[i][j] = 0ull;

#define LOADG(kt, pa0, pa1, pb0, pb1) do {                                         \
        pa0 = *(const float4*)&W[(size_t)((kt) + kA) * DD + j0 + mA0 * 4];         \
        pa1 = *(const float4*)&W[(size_t)((kt) + kA) * DD + j0 + mA1 * 4];         \
        pb0 = *(const float4*)&Xb[(size_t)(s0 + nB) * DD + (kt) + kB0 * 4];        \
        pb1 = *(const float4*)&Xb[(size_t)(s0 + nB) * DD + (kt) + kB1 * 4];        \
    } while (0)

#define STORES(buf, pa0, pa1, pb0, pb1) do {                                       \
        *(float4*)&As[buf][kA][mA0 * 4] = pa0;                                     \
        *(float4*)&As[buf][kA][mA1 * 4] = pa1;                                     \
        Bs[buf][kB0 * 4 + 0][nB] = pb0.x;  Bs[buf][kB0 * 4 + 1][nB] = pb0.y;       \
        Bs[buf][kB0 * 4 + 2][nB] = pb0.z;  Bs[buf][kB0 * 4 + 3][nB] = pb0.w;       \
        Bs[buf][kB1 * 4 + 0][nB] = pb1.x;  Bs[buf][kB1 * 4 + 1][nB] = pb1.y;       \
        Bs[buf][kB1 * 4 + 2][nB] = pb1.z;  Bs[buf][kB1 * 4 + 3][nB] = pb1.w;       \
    } while (0)

    {
        float4 pa0, pa1, pb0, pb1;
        LOADG(0, pa0, pa1, pb0, pb1);
        STORES(0, pa0, pa1, pb0, pb1);
    }
    __syncthreads();

    int cur = 0;
    for (int kt = 0; kt < DD; kt += BK) {
        bool has = (kt + BK) < DD;
        float4 qa0, qa1, qb0, qb1;
        if (has) LOADG(kt + BK, qa0, qa1, qb0, qb1);

        // compute on buffer `cur`
#pragma unroll
        for (int k = 0; k < BK; k++) {
            unsigned long long a2[8], b2[4];
#pragma unroll
            for (int i = 0; i < 8; i++) {
                float a = As[cur][k][m0 + i];
                asm("mov.b64 %0, {%1, %1};" : "=l"(a2[i]) : "f"(a));
            }
#pragma unroll
            for (int j = 0; j < 4; j++)
                b2[j] = *(const unsigned long long*)&Bs[cur][k][n0 + 2 * j];
#pragma unroll
            for (int i = 0; i < 8; i++)
#pragma unroll
                for (int j = 0; j < 4; j++)
                    asm("fma.rn.f32x2 %0, %1, %2, %0;"
                        : "+l"(acc2[i][j]) : "l"(a2[i]), "l"(b2[j]));
        }

        if (has) STORES(cur ^ 1, qa0, qa1, qb0, qb1);
        __syncthreads();
        cur ^= 1;
    }

#pragma unroll
    for (int i = 0; i < 8; i++) {
        float bj = bias[j0 + m0 + i];
        float r[8];
#pragma unroll
        for (int j = 0; j < 4; j++) {
            float lo, hi;
            asm("mov.b64 {%0, %1}, %2;" : "=f"(lo), "=f"(hi) : "l"(acc2[i][j]));
            r[2 * j]     = lo + bj;
            r[2 * j + 1] = hi + bj;
        }
        float* row = Ct + (size_t)(b * DD + j0 + m0 + i) * SS + s0 + n0;
        *(float4*)row       = make_float4(r[0], r[1], r[2], r[3]);
        *(float4*)(row + 4) = make_float4(r[4], r[5], r[6], r[7]);
    }
#undef LOADG
#undef STORES
}

// ---------------- kernel 2: packed forward FFT of (q + i*k), per (b,h,d) ----------------
// Writes per-channel spectrum product Q[f]*conj(K[f]) into g_P (no atomics).
__global__ void fft_qk_kernel() {
    int bhd = blockIdx.x;                 // 0..4095, == b*D + h*64 + d
    const float* qr = g_Qt + (size_t)bhd * SS;
    const float* kr = g_Kt + (size_t)bhd * SS;

    __shared__ float2 z[2048];            // 16KB
    __shared__ float2 tw[1024];           // 8KB

    int tid = threadIdx.x;
    for (int i = tid; i < 1024; i += 256) tw[i] = g_twf[i];
    for (int s = tid; s < 2048; s += 256) {
        int rs = __brev((unsigned)s) >> 21;         // 11-bit reversal
        z[rs] = make_float2(qr[s], kr[s]);
    }
    __syncthreads();

    fft2048f(z, tw);

    // Unpack: Z = FFT(q + i k). Q[f] = (Z[f]+conj(Z[N-f]))/2, K[f] = (Z[f]-conj(Z[N-f]))/(2i)
    for (int f = tid; f < 2048; f += 256) {
        float2 Zf = z[f];
        float2 Zc = z[(2048 - f) & 2047];
        float Qr =  0.5f * (Zf.x + Zc.x);
        float Qi =  0.5f * (Zf.y - Zc.y);
        float Kr =  0.5f * (Zf.y + Zc.y);
        float Ki = -0.5f * (Zf.x - Zc.x);
        // P = Q * conj(K)
        g_P[(size_t)bhd * SS + f] = make_float2(Qr * Kr + Qi * Ki, Qi * Kr - Qr * Ki);
    }
}

// ---------------- kernel 3: reduce over d, inverse FFT, top-k, softmax, gather ----------------
__global__ void corr_topk_kernel(const float* __restrict__ xv,
                                 const float* __restrict__ wv,
                                 const float* __restrict__ bv) {
    int bh = blockIdx.x;       // 0..63
    int b = bh >> 4, h = bh & 15;

    __shared__ float2 z[2048];                      // 16KB
    __shared__ float2 tw[1024];                     // 8KB
    __shared__ unsigned long long key[2048];        // 16KB
    __shared__ float zv[1024];                      // 4KB
    __shared__ float red[256];                      // 1KB

    int tid = threadIdx.x;
    for (int i = tid; i < 1024; i += 256) tw[i] = g_twf[i];

    // Sum spectra over channels d; load conj(P) bit-reversed (iFFT via conj trick).
    const float2* Pbase = g_P + (size_t)bh * DH * SS;
    for (int f = tid; f < 2048; f += 256) {
        float sr = 0.0f, si = 0.0f;
        for (int d = 0; d < DH; d++) {
            float2 p = Pbase[(size_t)d * SS + f];
            sr += p.x;
            si += p.y;
        }
        int rf = __brev((unsigned)f) >> 21;
        z[rf] = make_float2(sr, -si);
    }
    __syncthreads();

    fft2048f(z, tw);

    // mean_corr[t] = Re(FFT(conj(P)))[t] / N / (dh*sqrt(dh));  N=2048, dh*sqrt(dh)=512
    // Encode as sortable 64-bit key: value desc primary, index asc on ties.
    for (int t = tid; t < 2048; t += 256) {
        float v = z[t].x * (1.0f / (2048.0f * 512.0f));
        key[t] = ((unsigned long long)fenc(v) << 32) | (unsigned)(2047 - t);
    }
    __syncthreads();

    // Bitonic sort, descending on the combined key (== lax.top_k order)
    for (int k = 2; k <= 2048; k <<= 1) {
        for (int j = k >> 1; j > 0; j >>= 1) {
            for (int t = tid; t < 2048; t += 256) {
                int ixj = t ^ j;
                if (ixj > t) {
                    unsigned long long A = key[t], Bv = key[ixj];
                    bool desc = ((t & k) == 0);
                    bool sw = desc ? (Bv > A) : (A > Bv);
                    if (sw) { key[t] = Bv; key[ixj] = A; }
                }
            }
            __syncthreads();
        }
    }

    // Softmax over top KTOP values
    float maxv = fdec((unsigned)(key[0] >> 32));
    float lsum = 0.0f;
    for (int k = tid; k < KTOP; k += 256) lsum += expf(fdec((unsigned)(key[k] >> 32)) - maxv);
    red[tid] = lsum;
    for (int off = 128; off > 0; off >>= 1) {
        __syncthreads();
        if (tid < off) red[tid] += red[tid + off];
    }
    __syncthreads();
    float total = red[0];
    __syncthreads();

    // z[k] = (weight_k, index_k) for k < KTOP (z free after key build)
    for (int k = tid; k < KTOP; k += 256) {
        unsigned long long K = key[k];
        float v = fdec((unsigned)(K >> 32));
        int idx = 2047 - (int)(K & 0xFFFFFFFFull);
        z[k] = make_float2(expf(v - maxv) / total, (float)idx);
    }
    __syncthreads();

    // zv[c] = sum_k w_k * xv[b, idx_k, c]
    for (int c = tid; c < DD; c += 256) {
        float acc = 0.0f;
        for (int k = 0; k < KTOP; k++) {
            float2 wk = z[k];
            acc += wk.x * xv[((size_t)(b * SS + (int)wk.y)) * DD + c];
        }
        zv[c] = acc;
    }
    __syncthreads();

    // attended[j = h*64+dd] = sum_c zv[c] * wv[c, j] + bv[j]   (sum of weights == 1)
    if (tid < DH) {
        int j = h * DH + tid;
        float acc = 0.0f;
        for (int c = 0; c < DD; c++) acc += zv[c] * wv[(size_t)c * DD + j];
        g_att[b * DD + j] = acc + bv[j];
    }
}

// ---------------- kernel 4: y[b] = attended[b] @ wo + bo ----------------
__global__ void proj_y_kernel(const float* __restrict__ wo, const float* __restrict__ bo) {
    int b = blockIdx.x;
    int j = threadIdx.x;  // 1024 threads
    __shared__ float av[DD];
    av[j] = g_att[b * DD + j];
    __syncthreads();
    float acc = 0.0f;
    for (int i = 0; i < DD; i++) acc += av[i] * wo[(size_t)i * DD + j];
    g_y[b * DD + j] = acc + bo[j];
}

// ---------------- kernel 5: broadcast across sequence ----------------
__global__ void bcast_kernel(float* __restrict__ out) {
    int idx = blockIdx.x * blockDim.x + threadIdx.x;  // over B*S*D/4 float4s
    int j4 = idx & 255;          // D/4 = 256
    int bs = idx >> 8;           // 0..8191
    int b  = bs >> 11;           // /2048
    ((float4*)out)[idx] = ((const float4*)g_y)[b * 256 + j4];
}

// ---------------- launch ----------------
extern "C" void kernel_launch(void* const* d_in, const int* in_sizes, int n_in,
                              void* d_out, int out_size) {
    const float* xq = (const float*)d_in[0];
    const float* xk = (const float*)d_in[1];
    const float* xv = (const float*)d_in[2];
    const float* wq = (const float*)d_in[3];
    const float* bq = (const float*)d_in[4];
    const float* wk = (const float*)d_in[5];
    const float* bk = (const float*)d_in[6];
    const float* wv = (const float*)d_in[7];
    const float* bv = (const float*)d_in[8];
    const float* wo = (const float*)d_in[9];
    const float* bo = (const float*)d_in[10];
    float* out = (float*)d_out;

    tw_init_kernel<<<4, 256>>>();
    sgemm_tn_kernel<<<dim3(DD / BM, SS / BN, BB), 256>>>(xq, wq, bq, 0);
    sgemm_tn_kernel<<<dim3(DD / BM, SS / BN, BB), 256>>>(xk, wk, bk, 1);
    fft_qk_kernel<<<BB * DD, 256>>>();
    corr_topk_kernel<<<BB * HH, 256>>>(xv, wv, bv);
    proj_y_kernel<<<BB, DD>>>(wo, bo);
    bcast_kernel<<<(BB * SS * DD / 4) / 256, 256>>>(out);
}

// round 12
// speedup vs baseline: 1.0456x; 1.0456x over previous
#include <cuda_runtime.h>
#include <cuda_bf16.h>
#include <math.h>

// Problem constants
#define BB   4
#define SS   2048
#define DD   1024
#define HH   16
#define DH   64
#define KTOP 409        // max(S // 5, 1)

// ---------------- scratch (device globals; no allocation allowed) ----------------
__device__ float   g_Qt[(size_t)BB * DD * SS];   // Q transposed: [b*D + j][s]
__device__ float   g_Kt[(size_t)BB * DD * SS];   // K transposed
__device__ float2  g_P[(size_t)BB * DD * SS];    // per-(b,h,d) spectrum product Q*conj(K)
__device__ float   g_att[BB * DD];               // attended, flattened heads
__device__ float   g_y[BB * DD];                 // final per-batch output row
__device__ float2  g_twf[1024];                  // FFT twiddles exp(-2*pi*i*j/2048)

// ---------------- helpers ----------------
// In-place radix-2 DIT FFT of 2048 complex floats in shared memory.
// Input must be pre-bit-reversed. 256 threads. Caller syncs before the call.
__device__ void fft2048f(float2* z, const float2* tw) {
    int tid = threadIdx.x;
    for (int half = 1; half < 2048; half <<= 1) {
        int step = 1024 / half;  // twiddle stride
        for (int jj = tid; jj < 1024; jj += 256) {
            int p  = jj & (half - 1);
            int i0 = ((jj ^ p) << 1) | p;  // (jj - p)*2 + p
            int i1 = i0 + half;
            float2 w = tw[p * step];
            float2 v = z[i1];
            float tr = w.x * v.x - w.y * v.y;
            float ti = w.x * v.y + w.y * v.x;
            float2 u = z[i0];
            z[i0] = make_float2(u.x + tr, u.y + ti);
            z[i1] = make_float2(u.x - tr, u.y - ti);
        }
        __syncthreads();
    }
}

// Order-preserving float <-> uint encode (ascending uint order == ascending float order)
__device__ __forceinline__ unsigned int fenc(float v) {
    unsigned int u = __float_as_uint(v);
    return (u & 0x80000000u) ? ~u : (u | 0x80000000u);
}
__device__ __forceinline__ float fdec(unsigned int e) {
    unsigned int u = (e & 0x80000000u) ? (e & 0x7FFFFFFFu) : ~e;
    return __uint_as_float(u);
}

// ---------------- kernel 0: twiddle table ----------------
__global__ void tw_init_kernel() {
    int i = blockIdx.x * blockDim.x + threadIdx.x;
    if (i < 1024) {
        double ang = -2.0 * 3.14159265358979323846 * (double)i / 2048.0;
        g_twf[i] = make_float2((float)cos(ang), (float)sin(ang));
    }
}

// ---------------- kernel 1: SGEMM, transposed output, f32x2 packed FMA ----------------
// Ct[(b*D + j)*S + s] = sum_c X[(b*S+s)*D + c] * W[c*D + j] + bias[j]
#define BM 128
#define BN 128
#define BK 16
__global__ __launch_bounds__(256, 2)
void sgemm_tn_kernel(const float* __restrict__ X, const float* __restrict__ W,
                     const float* __restrict__ bias, int which) {
    float* Ct = which ? g_Kt : g_Qt;
    int b  = blockIdx.z;
    int j0 = blockIdx.x * BM;
    int s0 = blockIdx.y * BN;
    const float* Xb = X + (size_t)b * SS * DD;

    __shared__ __align__(16) float As[2][BK][BM];  // As[.][k][m] = W[(kt+k)*D + j0+m]
    __shared__ __align__(16) float Bs[2][BK][BN];  // Bs[.][k][n] = Xb[(s0+n)*D + kt+k]

    int tid = threadIdx.x;
    int tx = tid & 15, ty = tid >> 4;
    int m0 = tx * 8, n0 = ty * 8;

    // loader indices: two float4 loads each for A and B per thread
    int kA = tid >> 4;                 // same for both A loads
    int mA0 = (tid * 2) & 31;
    int mA1 = mA0 + 1;
    int nB = tid >> 1;                 // same for both B loads
    int kB0 = (tid * 2) & 3;
    int kB1 = kB0 + 1;

    unsigned long long acc2[8][4];     // packed f32x2 accumulators (m, n-pairs)
#pragma unroll
    for (int i = 0; i < 8; i++)
#pragma unroll
        for (int j = 0; j < 4; j++) acc2[i][j] = 0ull;

#define LOADG(kt, pa0, pa1, pb0, pb1) do {                                         \
        pa0 = *(const float4*)&W[(size_t)((kt) + kA) * DD + j0 + mA0 * 4];         \
        pa1 = *(const float4*)&W[(size_t)((kt) + kA) * DD + j0 + mA1 * 4];         \
        pb0 = *(const float4*)&Xb[(size_t)(s0 + nB) * DD + (kt) + kB0 * 4];        \
        pb1 = *(const float4*)&Xb[(size_t)(s0 + nB) * DD + (kt) + kB1 * 4];        \
    } while (0)

#define STORES(buf, pa0, pa1, pb0, pb1) do {                                       \
        *(float4*)&As[buf][kA][mA0 * 4] = pa0;                                     \
        *(float4*)&As[buf][kA][mA1 * 4] = pa1;                                     \
        Bs[buf][kB0 * 4 + 0][nB] = pb0.x;  Bs[buf][kB0 * 4 + 1][nB] = pb0.y;       \
        Bs[buf][kB0 * 4 + 2][nB] = pb0.z;  Bs[buf][kB0 * 4 + 3][nB] = pb0.w;       \
        Bs[buf][kB1 * 4 + 0][nB] = pb1.x;  Bs[buf][kB1 * 4 + 1][nB] = pb1.y;       \
        Bs[buf][kB1 * 4 + 2][nB] = pb1.z;  Bs[buf][kB1 * 4 + 3][nB] = pb1.w;       \
    } while (0)

    {
        float4 pa0, pa1, pb0, pb1;
        LOADG(0, pa0, pa1, pb0, pb1);
        STORES(0, pa0, pa1, pb0, pb1);
    }
    __syncthreads();

    int cur = 0;
    for (int kt = 0; kt < DD; kt += BK) {
        bool has = (kt + BK) < DD;
        float4 qa0, qa1, qb0, qb1;
        if (has) LOADG(kt + BK, qa0, qa1, qb0, qb1);

        // compute on buffer `cur`
#pragma unroll
        for (int k = 0; k < BK; k++) {
            unsigned long long a2[8], b2[4];
#pragma unroll
            for (int i = 0; i < 8; i++) {
                float a = As[cur][k][m0 + i];
                asm("mov.b64 %0, {%1, %1};" : "=l"(a2[i]) : "f"(a));
            }
#pragma unroll
            for (int j = 0; j < 4; j++)
                b2[j] = *(const unsigned long long*)&Bs[cur][k][n0 + 2 * j];
#pragma unroll
            for (int i = 0; i < 8; i++)
#pragma unroll
                for (int j = 0; j < 4; j++)
                    asm("fma.rn.f32x2 %0, %1, %2, %0;"
                        : "+l"(acc2[i][j]) : "l"(a2[i]), "l"(b2[j]));
        }

        if (has) STORES(cur ^ 1, qa0, qa1, qb0, qb1);
        __syncthreads();
        cur ^= 1;
    }

#pragma unroll
    for (int i = 0; i < 8; i++) {
        float bj = bias[j0 + m0 + i];
        float r[8];
#pragma unroll
        for (int j = 0; j < 4; j++) {
            float lo, hi;
            asm("mov.b64 {%0, %1}, %2;" : "=f"(lo), "=f"(hi) : "l"(acc2[i][j]));
            r[2 * j]     = lo + bj;
            r[2 * j + 1] = hi + bj;
        }
        float* row = Ct + (size_t)(b * DD + j0 + m0 + i) * SS + s0 + n0;
        *(float4*)row       = make_float4(r[0], r[1], r[2], r[3]);
        *(float4*)(row + 4) = make_float4(r[4], r[5], r[6], r[7]);
    }
#undef LOADG
#undef STORES
}

// ---------------- kernel 2: packed forward FFT of (q + i*k), per (b,h,d) ----------------
// Writes per-channel spectrum product Q[f]*conj(K[f]) into g_P (no atomics).
__global__ void fft_qk_kernel() {
    int bhd = blockIdx.x;                 // 0..4095, == b*D + h*64 + d
    const float* qr = g_Qt + (size_t)bhd * SS;
    const float* kr = g_Kt + (size_t)bhd * SS;

    __shared__ float2 z[2048];            // 16KB
    __shared__ float2 tw[1024];           // 8KB

    int tid = threadIdx.x;
    for (int i = tid; i < 1024; i += 256) tw[i] = g_twf[i];
    for (int s = tid; s < 2048; s += 256) {
        int rs = __brev((unsigned)s) >> 21;         // 11-bit reversal
        z[rs] = make_float2(qr[s], kr[s]);
    }
    __syncthreads();

    fft2048f(z, tw);

    // Unpack: Z = FFT(q + i k). Q[f] = (Z[f]+conj(Z[N-f]))/2, K[f] = (Z[f]-conj(Z[N-f]))/(2i)
    for (int f = tid; f < 2048; f += 256) {
        float2 Zf = z[f];
        float2 Zc = z[(2048 - f) & 2047];
        float Qr =  0.5f * (Zf.x + Zc.x);
        float Qi =  0.5f * (Zf.y - Zc.y);
        float Kr =  0.5f * (Zf.y + Zc.y);
        float Ki = -0.5f * (Zf.x - Zc.x);
        // P = Q * conj(K)
        g_P[(size_t)bhd * SS + f] = make_float2(Qr * Kr + Qi * Ki, Qi * Kr - Qr * Ki);
    }
}

// ---------------- kernel 3: reduce over d, inverse FFT, top-k, softmax, gather ----------------
__global__ void corr_topk_kernel(const float* __restrict__ xv,
                                 const float* __restrict__ wv,
                                 const float* __restrict__ bv) {
    int bh = blockIdx.x;       // 0..63
    int b = bh >> 4, h = bh & 15;

    __shared__ float2 z[2048];                      // 16KB
    __shared__ float2 tw[1024];                     // 8KB
    __shared__ unsigned long long key[2048];        // 16KB
    __shared__ float zv[1024];                      // 4KB
    __shared__ float red[256];                      // 1KB

    int tid = threadIdx.x;
    for (int i = tid; i < 1024; i += 256) tw[i] = g_twf[i];

    // Sum spectra over channels d; load conj(P) bit-reversed (iFFT via conj trick).
    const float2* Pbase = g_P + (size_t)bh * DH * SS;
    for (int f = tid; f < 2048; f += 256) {
        float sr = 0.0f, si = 0.0f;
        for (int d = 0; d < DH; d++) {
            float2 p = Pbase[(size_t)d * SS + f];
            sr += p.x;
            si += p.y;
        }
        int rf = __brev((unsigned)f) >> 21;
        z[rf] = make_float2(sr, -si);
    }
    __syncthreads();

    fft2048f(z, tw);

    // mean_corr[t] = Re(FFT(conj(P)))[t] / N / (dh*sqrt(dh));  N=2048, dh*sqrt(dh)=512
    // Encode as sortable 64-bit key: value desc primary, index asc on ties.
    for (int t = tid; t < 2048; t += 256) {
        float v = z[t].x * (1.0f / (2048.0f * 512.0f));
        key[t] = ((unsigned long long)fenc(v) << 32) | (unsigned)(2047 - t);
    }
    __syncthreads();

    // Bitonic sort, descending on the combined key (== lax.top_k order)
    for (int k = 2; k <= 2048; k <<= 1) {
        for (int j = k >> 1; j > 0; j >>= 1) {
            for (int t = tid; t < 2048; t += 256) {
                int ixj = t ^ j;
                if (ixj > t) {
                    unsigned long long A = key[t], Bv = key[ixj];
                    bool desc = ((t & k) == 0);
                    bool sw = desc ? (Bv > A) : (A > Bv);
                    if (sw) { key[t] = Bv; key[ixj] = A; }
                }
            }
            __syncthreads();
        }
    }

    // Softmax over top KTOP values
    float maxv = fdec((unsigned)(key[0] >> 32));
    float lsum = 0.0f;
    for (int k = tid; k < KTOP; k += 256) lsum += expf(fdec((unsigned)(key[k] >> 32)) - maxv);
    red[tid] = lsum;
    for (int off = 128; off > 0; off >>= 1) {
        __syncthreads();
        if (tid < off) red[tid] += red[tid + off];
    }
    __syncthreads();
    float total = red[0];
    __syncthreads();

    // z[k] = (weight_k, index_k) for k < KTOP (z free after key build)
    for (int k = tid; k < KTOP; k += 256) {
        unsigned long long K = key[k];
        float v = fdec((unsigned)(K >> 32));
        int idx = 2047 - (int)(K & 0xFFFFFFFFull);
        z[k] = make_float2(expf(v - maxv) / total, (float)idx);
    }
    __syncthreads();

    // zv[c] = sum_k w_k * xv[b, idx_k, c]
    for (int c = tid; c < DD; c += 256) {
        float acc = 0.0f;
        for (int k = 0; k < KTOP; k++) {
            float2 wk = z[k];
            acc += wk.x * xv[((size_t)(b * SS + (int)wk.y)) * DD + c];
        }
        zv[c] = acc;
    }
    __syncthreads();

    // attended[j = h*64+dd] = sum_c zv[c] * wv[c, j] + bv[j]   (sum of weights == 1)
    if (tid < DH) {
        int j = h * DH + tid;
        float acc = 0.0f;
        for (int c = 0; c < DD; c++) acc += zv[c] * wv[(size_t)c * DD + j];
        g_att[b * DD + j] = acc + bv[j];
    }
}

// ---------------- kernel 4: y[b] = attended[b] @ wo + bo ----------------
__global__ void proj_y_kernel(const float* __restrict__ wo, const float* __restrict__ bo) {
    int b = blockIdx.x;
    int j = threadIdx.x;  // 1024 threads
    __shared__ float av[DD];
    av[j] = g_att[b * DD + j];
    __syncthreads();
    float acc = 0.0f;
    for (int i = 0; i < DD; i++) acc += av[i] * wo[(size_t)i * DD + j];
    g_y[b * DD + j] = acc + bo[j];
}

// ---------------- kernel 5: broadcast across sequence ----------------
__global__ void bcast_kernel(float* __restrict__ out) {
    int idx = blockIdx.x * blockDim.x + threadIdx.x;  // over B*S*D/4 float4s
    int j4 = idx & 255;          // D/4 = 256
    int bs = idx >> 8;           // 0..8191
    int b  = bs >> 11;           // /2048
    ((float4*)out)[idx] = ((const float4*)g_y)[b * 256 + j4];
}

// ---------------- launch ----------------
extern "C" void kernel_launch(void* const* d_in, const int* in_sizes, int n_in,
                              void* d_out, int out_size) {
    const float* xq = (const float*)d_in[0];
    const float* xk = (const float*)d_in[1];
    const float* xv = (const float*)d_in[2];
    const float* wq = (const float*)d_in[3];
    const float* bq = (const float*)d_in[4];
    const float* wk = (const float*)d_in[5];
    const float* bk = (const float*)d_in[6];
    const float* wv = (const float*)d_in[7];
    const float* bv = (const float*)d_in[8];
    const float* wo = (const float*)d_in[9];
    const float* bo = (const float*)d_in[10];
    float* out = (float*)d_out;

    tw_init_kernel<<<4, 256>>>();
    sgemm_tn_kernel<<<dim3(DD / BM, SS / BN, BB), 256>>>(xq, wq, bq, 0);
    sgemm_tn_kernel<<<dim3(DD / BM, SS / BN, BB), 256>>>(xk, wk, bk, 1);
    fft_qk_kernel<<<BB * DD, 256>>>();
    corr_topk_kernel<<<BB * HH, 256>>>(xv, wv, bv);
    proj_y_kernel<<<BB, DD>>>(wo, bo);
    bcast_kernel<<<(BB * SS * DD / 4) / 256, 256>>>(out);
}

// round 14
// speedup vs baseline: 1.6843x; 1.6108x over previous
#include <cuda_runtime.h>
#include <cuda_bf16.h>
#include <math.h>
#include <stdint.h>

// Problem constants
#define BB   4
#define SS   2048
#define DD   1024
#define HH   16
#define DH   64
#define KTOP 409        // max(S // 5, 1)

// ---------------- scratch (device globals; no allocation allowed) ----------------
__device__ float   g_Qt[(size_t)BB * DD * SS];   // Q transposed: [b*D + j][s]
__device__ float   g_Kt[(size_t)BB * DD * SS];   // K transposed
__device__ float2  g_P[(size_t)BB * DD * SS];    // per-(b,h,d) spectrum product Q*conj(K)
__device__ float   g_Wqt[(size_t)DD * DD];       // wq transposed: [j][c]
__device__ float   g_Wkt[(size_t)DD * DD];       // wk transposed: [j][c]
__device__ float   g_att[BB * DD];               // attended, flattened heads
__device__ float   g_y[BB * DD];                 // final per-batch output row
__device__ float2  g_twf[1024];                  // FFT twiddles exp(-2*pi*i*j/2048)

// ---------------- PTX helpers (sm_80-compatible: mma.sync + ldmatrix only) -------
__device__ __forceinline__ uint32_t smem_u32(const void* p) {
    uint32_t a;
    asm("{ .reg .u64 t; cvta.to.shared.u64 t, %1; cvt.u32.u64 %0, t; }" : "=r"(a) : "l"(p));
    return a;
}
__device__ __forceinline__ void ldsm_x4(uint32_t (&r)[4], uint32_t addr) {
    asm volatile("ldmatrix.sync.aligned.m8n8.x4.shared.b16 {%0,%1,%2,%3}, [%4];"
        : "=r"(r[0]), "=r"(r[1]), "=r"(r[2]), "=r"(r[3]) : "r"(addr));
}
__device__ __forceinline__ void mma_bf16(float (&c)[4], const uint32_t (&a)[4],
                                         uint32_t b0, uint32_t b1) {
    asm volatile(
        "mma.sync.aligned.m16n8k16.row.col.f32.bf16.bf16.f32 "
        "{%0,%1,%2,%3}, {%4,%5,%6,%7}, {%8,%9}, {%0,%1,%2,%3};"
        : "+f"(c[0]), "+f"(c[1]), "+f"(c[2]), "+f"(c[3])
        : "r"(a[0]), "r"(a[1]), "r"(a[2]), "r"(a[3]), "r"(b0), "r"(b1));
}

// Split one float4 into bf16 hi/lo pairs and store 8B each into hi/lo tiles.
__device__ __forceinline__ void split8(char* ht, char* lt, int off, float4 v) {
    __nv_bfloat162 h0 = __float22bfloat162_rn(make_float2(v.x, v.y));
    __nv_bfloat162 h1 = __float22bfloat162_rn(make_float2(v.z, v.w));
    float2 f0 = __bfloat1622float2(h0), f1 = __bfloat1622float2(h1);
    __nv_bfloat162 l0 = __float22bfloat162_rn(make_float2(v.x - f0.x, v.y - f0.y));
    __nv_bfloat162 l1 = __float22bfloat162_rn(make_float2(v.z - f1.x, v.w - f1.y));
    uint2 H, L;
    H.x = *(uint32_t*)&h0; H.y = *(uint32_t*)&h1;
    L.x = *(uint32_t*)&l0; L.y = *(uint32_t*)&l1;
    *(uint2*)(ht + off) = H;
    *(uint2*)(lt + off) = L;
}

// ---------------- generic helpers ----------------
__device__ void fft2048f(float2* z, const float2* tw) {
    int tid = threadIdx.x;
    for (int half = 1; half < 2048; half <<= 1) {
        int step = 1024 / half;
        for (int jj = tid; jj < 1024; jj += 256) {
            int p  = jj & (half - 1);
            int i0 = ((jj ^ p) << 1) | p;
            int i1 = i0 + half;
            float2 w = tw[p * step];
            float2 v = z[i1];
            float tr = w.x * v.x - w.y * v.y;
            float ti = w.x * v.y + w.y * v.x;
            float2 u = z[i0];
            z[i0] = make_float2(u.x + tr, u.y + ti);
            z[i1] = make_float2(u.x - tr, u.y - ti);
        }
        __syncthreads();
    }
}
__device__ __forceinline__ unsigned int fenc(float v) {
    unsigned int u = __float_as_uint(v);
    return (u & 0x80000000u) ? ~u : (u | 0x80000000u);
}
__device__ __forceinline__ float fdec(unsigned int e) {
    unsigned int u = (e & 0x80000000u) ? (e & 0x7FFFFFFFu) : ~e;
    return __uint_as_float(u);
}

// ---------------- kernel 0: twiddle table ----------------
__global__ void tw_init_kernel() {
    int i = blockIdx.x * blockDim.x + threadIdx.x;
    if (i < 1024) {
        double ang = -2.0 * 3.14159265358979323846 * (double)i / 2048.0;
        g_twf[i] = make_float2((float)cos(ang), (float)sin(ang));
    }
}

// ---------------- kernel 0b: W transpose (Wt[j][c] = W[c][j]) ----------------
__global__ void wtrans_kernel(const float* __restrict__ W, float* __restrict__ Wt) {
    __shared__ float t[32][33];
    int bx = blockIdx.x * 32, by = blockIdx.y * 32;
    int x = threadIdx.x, y4 = threadIdx.y;  // block (32,8)
#pragma unroll
    for (int i = 0; i < 32; i += 8)
        t[y4 + i][x] = W[(size_t)(by + y4 + i) * DD + bx + x];
    __syncthreads();
#pragma unroll
    for (int i = 0; i < 32; i += 8)
        Wt[(size_t)(bx + y4 + i) * DD + by + x] = t[x][y4 + i];
}

// ---------------- kernel 1: bf16x3-split tensor-core GEMM (mma.sync) ----------------
// Ct[(b*D + j)*S + s] = sum_c Wt[j][c] * X[(b*S+s)*D + c] + bias[j]
// CTA tile 128(m=j) x 128(n=s), K staged 16 fp32 at a time, split into
// bf16 hi/lo in smem; C = Ah*Bh + Ah*Bl + Al*Bh (error ~2^-16 per element).
#define ROWB   48                    // padded row stride (bytes): conflict-free ldmatrix
#define TILE_B (128 * ROWB)          // 6144 B per bf16 tile (128 rows x 16 k)
#define STAGE_B (4 * TILE_B)         // Ah, Al, Bh, Bl

__global__ __launch_bounds__(256)
void gemm_mma_kernel(const float* __restrict__ X, const float* __restrict__ Wt,
                     const float* __restrict__ bias, float* __restrict__ Ct) {
    __shared__ __align__(16) char sm[2 * STAGE_B];   // 49152 B

    const int tid  = threadIdx.x;
    const int lane = tid & 31, wid = tid >> 5;
    const int mw = wid & 3, nw = wid >> 2;           // 4 x 2 warp grid
    const int b  = blockIdx.z;
    const int j0 = blockIdx.x * 128;
    const int s0 = blockIdx.y * 128;
    const float* Xb = X + (size_t)b * SS * DD;

    // ---- fill mapping: 512 float4 chunks per operand, 2 per thread ----
    const int ch0 = tid, ch1 = tid + 256;
    const int rA0 = ch0 >> 2, c40 = ch0 & 3;
    const int rA1 = ch1 >> 2, c41 = ch1 & 3;
    const float* pA0 = Wt + (size_t)(j0 + rA0) * DD + c40 * 4;
    const float* pA1 = Wt + (size_t)(j0 + rA1) * DD + c41 * 4;
    const float* pB0 = Xb + (size_t)(s0 + rA0) * DD + c40 * 4;
    const float* pB1 = Xb + (size_t)(s0 + rA1) * DD + c41 * 4;
    const int off0 = rA0 * ROWB + c40 * 8;
    const int off1 = rA1 * ROWB + c41 * 8;

    // ---- ldmatrix lane addressing ----
    uint32_t smb = smem_u32(sm);
    const int aoff = (lane & 15) * ROWB + (lane >> 4) * 16;   // m-rows 0-15, k-half
    const int am0 = (mw * 32 +  0) * ROWB + aoff;
    const int am1 = (mw * 32 + 16) * ROWB + aoff;
    const int nloc = (lane & 7) + ((lane >> 4) << 3);          // n-row within 16
    const int boff = ((lane >> 3) & 1) * 16;                   // k-half
    int bn[4];
#pragma unroll
    for (int nf = 0; nf < 4; nf++)
        bn[nf] = (nw * 64 + nf * 16 + nloc) * ROWB + boff;

    float acc[2][8][4];
#pragma unroll
    for (int mi = 0; mi < 2; mi++)
#pragma unroll
        for (int ni = 0; ni < 8; ni++)
#pragma unroll
            for (int q = 0; q < 4; q++) acc[mi][ni][q] = 0.0f;

#define FILL(buf, va0, va1, vb0, vb1) do {                              \
        char* base = sm + (buf) * STAGE_B;                              \
        split8(base,              base + TILE_B,     off0, va0);        \
        split8(base,              base + TILE_B,     off1, va1);        \
        split8(base + 2 * TILE_B, base + 3 * TILE_B, off0, vb0);        \
        split8(base + 2 * TILE_B, base + 3 * TILE_B, off1, vb1);        \
    } while (0)

    // prologue: stage 0
    {
        float4 va0 = *(const float4*)pA0;
        float4 va1 = *(const float4*)pA1;
        float4 vb0 = *(const float4*)pB0;
        float4 vb1 = *(const float4*)pB1;
        FILL(0, va0, va1, vb0, vb1);
    }
    __syncthreads();

    const int NST = DD / 16;   // 64 stages
    for (int s = 0; s < NST; s++) {
        int buf = s & 1;
        float4 na0, na1, nb0, nb1;
        if (s + 1 < NST) {
            na0 = *(const float4*)(pA0 + (s + 1) * 16);
            na1 = *(const float4*)(pA1 + (s + 1) * 16);
            nb0 = *(const float4*)(pB0 + (s + 1) * 16);
            nb1 = *(const float4*)(pB1 + (s + 1) * 16);
        }

        uint32_t base = smb + buf * STAGE_B;
#pragma unroll
        for (int combo = 0; combo < 3; combo++) {
            // combo 0: Ah*Bh, 1: Ah*Bl, 2: Al*Bh
            uint32_t at = base + (combo == 2 ? TILE_B : 0);
            uint32_t bt = base + 2 * TILE_B + (combo == 1 ? TILE_B : 0);
            uint32_t a0[4], a1[4];
            ldsm_x4(a0, at + am0);
            ldsm_x4(a1, at + am1);
#pragma unroll
            for (int nf = 0; nf < 4; nf++) {
                uint32_t bb[4];
                ldsm_x4(bb, bt + bn[nf]);
                mma_bf16(acc[0][2 * nf],     a0, bb[0], bb[1]);
                mma_bf16(acc[0][2 * nf + 1], a0, bb[2], bb[3]);
                mma_bf16(acc[1][2 * nf],     a1, bb[0], bb[1]);
                mma_bf16(acc[1][2 * nf + 1], a1, bb[2], bb[3]);
            }
        }

        if (s + 1 < NST) FILL(buf ^ 1, na0, na1, nb0, nb1);
        __syncthreads();
    }
#undef FILL

    // ---- epilogue: bias add + store ----
    const int grp = lane >> 2, qd = lane & 3;
#pragma unroll
    for (int mi = 0; mi < 2; mi++) {
#pragma unroll
        for (int half = 0; half < 2; half++) {
            int j = j0 + mw * 32 + mi * 16 + grp + half * 8;
            float bj = bias[j];
            float* dst = Ct + ((size_t)(b * DD + j)) * SS + s0 + nw * 64 + qd * 2;
#pragma unroll
            for (int ni = 0; ni < 8; ni++) {
                float2 v = make_float2(acc[mi][ni][half * 2 + 0] + bj,
                                       acc[mi][ni][half * 2 + 1] + bj);
                *(float2*)(dst + ni * 8) = v;
            }
        }
    }
}

// ---------------- kernel 2: packed forward FFT of (q + i*k), per (b,h,d) ----------------
__global__ void fft_qk_kernel() {
    int bhd = blockIdx.x;
    const float* qr = g_Qt + (size_t)bhd * SS;
    const float* kr = g_Kt + (size_t)bhd * SS;

    __shared__ float2 z[2048];
    __shared__ float2 tw[1024];

    int tid = threadIdx.x;
    for (int i = tid; i < 1024; i += 256) tw[i] = g_twf[i];
    for (int s = tid; s < 2048; s += 256) {
        int rs = __brev((unsigned)s) >> 21;
        z[rs] = make_float2(qr[s], kr[s]);
    }
    __syncthreads();

    fft2048f(z, tw);

    for (int f = tid; f < 2048; f += 256) {
        float2 Zf = z[f];
        float2 Zc = z[(2048 - f) & 2047];
        float Qr =  0.5f * (Zf.x + Zc.x);
        float Qi =  0.5f * (Zf.y - Zc.y);
        float Kr =  0.5f * (Zf.y + Zc.y);
        float Ki = -0.5f * (Zf.x - Zc.x);
        g_P[(size_t)bhd * SS + f] = make_float2(Qr * Kr + Qi * Ki, Qi * Kr - Qr * Ki);
    }
}

// ---------------- kernel 3: reduce over d, inverse FFT, top-k, softmax, gather ----------------
__global__ void corr_topk_kernel(const float* __restrict__ xv,
                                 const float* __restrict__ wv,
                                 const float* __restrict__ bv) {
    int bh = blockIdx.x;
    int b = bh >> 4, h = bh & 15;

    __shared__ float2 z[2048];
    __shared__ float2 tw[1024];
    __shared__ unsigned long long key[2048];
    __shared__ float zv[1024];
    __shared__ float red[256];

    int tid = threadIdx.x;
    for (int i = tid; i < 1024; i += 256) tw[i] = g_twf[i];

    const float2* Pbase = g_P + (size_t)bh * DH * SS;
    for (int f = tid; f < 2048; f += 256) {
        float sr = 0.0f, si = 0.0f;
        for (int d = 0; d < DH; d++) {
            float2 p = Pbase[(size_t)d * SS + f];
            sr += p.x;
            si += p.y;
        }
        int rf = __brev((unsigned)f) >> 21;
        z[rf] = make_float2(sr, -si);
    }
    __syncthreads();

    fft2048f(z, tw);

    for (int t = tid; t < 2048; t += 256) {
        float v = z[t].x * (1.0f / (2048.0f * 512.0f));
        key[t] = ((unsigned long long)fenc(v) << 32) | (unsigned)(2047 - t);
    }
    __syncthreads();

    for (int k = 2; k <= 2048; k <<= 1) {
        for (int j = k >> 1; j > 0; j >>= 1) {
            for (int t = tid; t < 2048; t += 256) {
                int ixj = t ^ j;
                if (ixj > t) {
                    unsigned long long A = key[t], Bv = key[ixj];
                    bool desc = ((t & k) == 0);
                    bool sw = desc ? (Bv > A) : (A > Bv);
                    if (sw) { key[t] = Bv; key[ixj] = A; }
                }
            }
            __syncthreads();
        }
    }

    float maxv = fdec((unsigned)(key[0] >> 32));
    float lsum = 0.0f;
    for (int k = tid; k < KTOP; k += 256) lsum += expf(fdec((unsigned)(key[k] >> 32)) - maxv);
    red[tid] = lsum;
    for (int off = 128; off > 0; off >>= 1) {
        __syncthreads();
        if (tid < off) red[tid] += red[tid + off];
    }
    __syncthreads();
    float total = red[0];
    __syncthreads();

    for (int k = tid; k < KTOP; k += 256) {
        unsigned long long K = key[k];
        float v = fdec((unsigned)(K >> 32));
        int idx = 2047 - (int)(K & 0xFFFFFFFFull);
        z[k] = make_float2(expf(v - maxv) / total, (float)idx);
    }
    __syncthreads();

    for (int c = tid; c < DD; c += 256) {
        float acc = 0.0f;
        for (int k = 0; k < KTOP; k++) {
            float2 wk = z[k];
            acc += wk.x * xv[((size_t)(b * SS + (int)wk.y)) * DD + c];
        }
        zv[c] = acc;
    }
    __syncthreads();

    if (tid < DH) {
        int j = h * DH + tid;
        float acc = 0.0f;
        for (int c = 0; c < DD; c++) acc += zv[c] * wv[(size_t)c * DD + j];
        g_att[b * DD + j] = acc + bv[j];
    }
}

// ---------------- kernel 4: y[b] = attended[b] @ wo + bo ----------------
__global__ void proj_y_kernel(const float* __restrict__ wo, const float* __restrict__ bo) {
    int b = blockIdx.x;
    int j = threadIdx.x;
    __shared__ float av[DD];
    av[j] = g_att[b * DD + j];
    __syncthreads();
    float acc = 0.0f;
    for (int i = 0; i < DD; i++) acc += av[i] * wo[(size_t)i * DD + j];
    g_y[b * DD + j] = acc + bo[j];
}

// ---------------- kernel 5: broadcast across sequence ----------------
__global__ void bcast_kernel(float* __restrict__ out) {
    int idx = blockIdx.x * blockDim.x + threadIdx.x;
    int j4 = idx & 255;
    int bs = idx >> 8;
    int b  = bs >> 11;
    ((float4*)out)[idx] = ((const float4*)g_y)[b * 256 + j4];
}

// ---------------- launch ----------------
extern "C" void kernel_launch(void* const* d_in, const int* in_sizes, int n_in,
                              void* d_out, int out_size) {
    const float* xq = (const float*)d_in[0];
    const float* xk = (const float*)d_in[1];
    const float* xv = (const float*)d_in[2];
    const float* wq = (const float*)d_in[3];
    const float* bq = (const float*)d_in[4];
    const float* wk = (const float*)d_in[5];
    const float* bk = (const float*)d_in[6];
    const float* wv = (const float*)d_in[7];
    const float* bv = (const float*)d_in[8];
    const float* wo = (const float*)d_in[9];
    const float* bo = (const float*)d_in[10];
    float* out = (float*)d_out;

    float* wqt; cudaGetSymbolAddress((void**)&wqt, g_Wqt);
    float* wkt; cudaGetSymbolAddress((void**)&wkt, g_Wkt);
    float* qt;  cudaGetSymbolAddress((void**)&qt,  g_Qt);
    float* kt;  cudaGetSymbolAddress((void**)&kt,  g_Kt);

    tw_init_kernel<<<4, 256>>>();
    wtrans_kernel<<<dim3(32, 32), dim3(32, 8)>>>(wq, wqt);
    wtrans_kernel<<<dim3(32, 32), dim3(32, 8)>>>(wk, wkt);
    gemm_mma_kernel<<<dim3(DD / 128, SS / 128, BB), 256>>>(xq, wqt, bq, qt);
    gemm_mma_kernel<<<dim3(DD / 128, SS / 128, BB), 256>>>(xk, wkt, bk, kt);
    fft_qk_kernel<<<BB * DD, 256>>>();
    corr_topk_kernel<<<BB * HH, 256>>>(xv, wv, bv);
    proj_y_kernel<<<BB, DD>>>(wo, bo);
    bcast_kernel<<<(BB * SS * DD / 4) / 256, 256>>>(out);
}

// round 15
// speedup vs baseline: 1.7462x; 1.0367x over previous
#include <cuda_runtime.h>
#include <cuda_bf16.h>
#include <math.h>
#include <stdint.h>

// Problem constants
#define BB   4
#define SS   2048
#define DD   1024
#define HH   16
#define DH   64
#define KTOP 409        // max(S // 5, 1)

// ---------------- scratch (device globals; no allocation allowed) ----------------
__device__ float   g_Qt[(size_t)BB * DD * SS];   // Q transposed: [b*D + j][s]
__device__ float   g_Kt[(size_t)BB * DD * SS];   // K transposed
__device__ float2  g_P[(size_t)BB * DD * SS];    // per-(b,h,d) spectrum product Q*conj(K)
__device__ float2  g_Ps[64 * SS];                // spectra reduced over d, per (b,h)
__device__ float2  g_wk[64 * 512];               // (weight, index) per (b,h), KTOP used
__device__ float   g_zv[64 * DD];                // weighted xv sums per (b,h)
__device__ float   g_Wqt[(size_t)DD * DD];       // wq transposed: [j][c]
__device__ float   g_Wkt[(size_t)DD * DD];       // wk transposed: [j][c]
__device__ float   g_att[BB * DD];               // attended, flattened heads
__device__ float   g_y[BB * DD];                 // final per-batch output row
__device__ float2  g_twf[1024];                  // FFT twiddles exp(-2*pi*i*j/2048)

// ---------------- PTX helpers (sm_80-compatible: mma.sync + ldmatrix only) -------
__device__ __forceinline__ uint32_t smem_u32(const void* p) {
    uint32_t a;
    asm("{ .reg .u64 t; cvta.to.shared.u64 t, %1; cvt.u32.u64 %0, t; }" : "=r"(a) : "l"(p));
    return a;
}
__device__ __forceinline__ void ldsm_x4(uint32_t (&r)[4], uint32_t addr) {
    asm volatile("ldmatrix.sync.aligned.m8n8.x4.shared.b16 {%0,%1,%2,%3}, [%4];"
        : "=r"(r[0]), "=r"(r[1]), "=r"(r[2]), "=r"(r[3]) : "r"(addr));
}
__device__ __forceinline__ void mma_bf16(float (&c)[4], const uint32_t (&a)[4],
                                         uint32_t b0, uint32_t b1) {
    asm volatile(
        "mma.sync.aligned.m16n8k16.row.col.f32.bf16.bf16.f32 "
        "{%0,%1,%2,%3}, {%4,%5,%6,%7}, {%8,%9}, {%0,%1,%2,%3};"
        : "+f"(c[0]), "+f"(c[1]), "+f"(c[2]), "+f"(c[3])
        : "r"(a[0]), "r"(a[1]), "r"(a[2]), "r"(a[3]), "r"(b0), "r"(b1));
}

// Split one float4 into bf16 hi/lo pairs and store 8B each into hi/lo tiles.
__device__ __forceinline__ void split8(char* ht, char* lt, int off, float4 v) {
    __nv_bfloat162 h0 = __float22bfloat162_rn(make_float2(v.x, v.y));
    __nv_bfloat162 h1 = __float22bfloat162_rn(make_float2(v.z, v.w));
    float2 f0 = __bfloat1622float2(h0), f1 = __bfloat1622float2(h1);
    __nv_bfloat162 l0 = __float22bfloat162_rn(make_float2(v.x - f0.x, v.y - f0.y));
    __nv_bfloat162 l1 = __float22bfloat162_rn(make_float2(v.z - f1.x, v.w - f1.y));
    uint2 H, L;
    H.x = *(uint32_t*)&h0; H.y = *(uint32_t*)&h1;
    L.x = *(uint32_t*)&l0; L.y = *(uint32_t*)&l1;
    *(uint2*)(ht + off) = H;
    *(uint2*)(lt + off) = L;
}

// ---------------- FFT helpers ----------------
__device__ __forceinline__ void bfly(float2& u, float2& v, float2 w) {
    float tr = w.x * v.x - w.y * v.y;
    float ti = w.x * v.y + w.y * v.x;
    float2 t = make_float2(u.x - tr, u.y - ti);
    u = make_float2(u.x + tr, u.y + ti);
    v = t;
}

// 2048-pt radix-2 DIT FFT, input pre-bit-reversed in z.
// Stages half=1..128 in smem; last 3 stages (256/512/1024) in registers.
// On return r[k] = Z[tid + 256*k]; z is NOT updated for those stages.
__device__ void fft2048_hybrid(float2* z, const float2* tw, float2 (&r)[8]) {
    int tid = threadIdx.x;
    for (int half = 1; half < 256; half <<= 1) {
        int step = 1024 / half;
        for (int jj = tid; jj < 1024; jj += 256) {
            int p  = jj & (half - 1);
            int i0 = ((jj ^ p) << 1) | p;
            int i1 = i0 + half;
            float2 w = tw[p * step];
            float2 v = z[i1];
            float tr = w.x * v.x - w.y * v.y;
            float ti = w.x * v.y + w.y * v.x;
            float2 u = z[i0];
            z[i0] = make_float2(u.x + tr, u.y + ti);
            z[i1] = make_float2(u.x - tr, u.y - ti);
        }
        __syncthreads();
    }
#pragma unroll
    for (int k = 0; k < 8; k++) r[k] = z[tid + 256 * k];
    // half = 256: p = tid, step = 4
    float2 w4 = tw[4 * tid];
    bfly(r[0], r[1], w4); bfly(r[2], r[3], w4);
    bfly(r[4], r[5], w4); bfly(r[6], r[7], w4);
    // half = 512: step = 2
    float2 w20 = tw[2 * tid], w21 = tw[2 * tid + 512];
    bfly(r[0], r[2], w20); bfly(r[1], r[3], w21);
    bfly(r[4], r[6], w20); bfly(r[5], r[7], w21);
    // half = 1024: step = 1
    bfly(r[0], r[4], tw[tid]);
    bfly(r[1], r[5], tw[tid + 256]);
    bfly(r[2], r[6], tw[tid + 512]);
    bfly(r[3], r[7], tw[tid + 768]);
}

__device__ __forceinline__ unsigned int fenc(float v) {
    unsigned int u = __float_as_uint(v);
    return (u & 0x80000000u) ? ~u : (u | 0x80000000u);
}
__device__ __forceinline__ float fdec(unsigned int e) {
    unsigned int u = (e & 0x80000000u) ? (e & 0x7FFFFFFFu) : ~e;
    return __uint_as_float(u);
}

// ---------------- kernel 0: twiddle table ----------------
__global__ void tw_init_kernel() {
    int i = blockIdx.x * blockDim.x + threadIdx.x;
    if (i < 1024) {
        double ang = -2.0 * 3.14159265358979323846 * (double)i / 2048.0;
        g_twf[i] = make_float2((float)cos(ang), (float)sin(ang));
    }
}

// ---------------- kernel 0b: W transpose (Wt[j][c] = W[c][j]) ----------------
__global__ void wtrans_kernel(const float* __restrict__ W, float* __restrict__ Wt) {
    __shared__ float t[32][33];
    int bx = blockIdx.x * 32, by = blockIdx.y * 32;
    int x = threadIdx.x, y4 = threadIdx.y;  // block (32,8)
#pragma unroll
    for (int i = 0; i < 32; i += 8)
        t[y4 + i][x] = W[(size_t)(by + y4 + i) * DD + bx + x];
    __syncthreads();
#pragma unroll
    for (int i = 0; i < 32; i += 8)
        Wt[(size_t)(bx + y4 + i) * DD + by + x] = t[x][y4 + i];
}

// ---------------- kernel 1: bf16x3-split tensor-core GEMM (mma.sync) ----------------
// Ct[(b*D + j)*S + s] = sum_c Wt[j][c] * X[(b*S+s)*D + c] + bias[j]
#define ROWB   48                    // padded row stride (bytes)
#define TILE_B (128 * ROWB)          // 6144 B per bf16 tile
#define STAGE_B (4 * TILE_B)         // Ah, Al, Bh, Bl

__global__ __launch_bounds__(256)
void gemm_mma_kernel(const float* __restrict__ X, const float* __restrict__ Wt,
                     const float* __restrict__ bias, float* __restrict__ Ct) {
    __shared__ __align__(16) char sm[2 * STAGE_B];   // 49152 B

    const int tid  = threadIdx.x;
    const int lane = tid & 31, wid = tid >> 5;
    const int mw = wid & 3, nw = wid >> 2;           // 4 x 2 warp grid
    const int b  = blockIdx.z;
    const int j0 = blockIdx.x * 128;
    const int s0 = blockIdx.y * 128;
    const float* Xb = X + (size_t)b * SS * DD;

    const int ch0 = tid, ch1 = tid + 256;
    const int rA0 = ch0 >> 2, c40 = ch0 & 3;
    const int rA1 = ch1 >> 2, c41 = ch1 & 3;
    const float* pA0 = Wt + (size_t)(j0 + rA0) * DD + c40 * 4;
    const float* pA1 = Wt + (size_t)(j0 + rA1) * DD + c41 * 4;
    const float* pB0 = Xb + (size_t)(s0 + rA0) * DD + c40 * 4;
    const float* pB1 = Xb + (size_t)(s0 + rA1) * DD + c41 * 4;
    const int off0 = rA0 * ROWB + c40 * 8;
    const int off1 = rA1 * ROWB + c41 * 8;

    uint32_t smb = smem_u32(sm);
    const int aoff = (lane & 15) * ROWB + (lane >> 4) * 16;
    const int am0 = (mw * 32 +  0) * ROWB + aoff;
    const int am1 = (mw * 32 + 16) * ROWB + aoff;
    const int nloc = (lane & 7) + ((lane >> 4) << 3);
    const int boff = ((lane >> 3) & 1) * 16;
    int bn[4];
#pragma unroll
    for (int nf = 0; nf < 4; nf++)
        bn[nf] = (nw * 64 + nf * 16 + nloc) * ROWB + boff;

    float acc[2][8][4];
#pragma unroll
    for (int mi = 0; mi < 2; mi++)
#pragma unroll
        for (int ni = 0; ni < 8; ni++)
#pragma unroll
            for (int q = 0; q < 4; q++) acc[mi][ni][q] = 0.0f;

#define FILL(buf, va0, va1, vb0, vb1) do {                              \
        char* base = sm + (buf) * STAGE_B;                              \
        split8(base,              base + TILE_B,     off0, va0);        \
        split8(base,              base + TILE_B,     off1, va1);        \
        split8(base + 2 * TILE_B, base + 3 * TILE_B, off0, vb0);        \
        split8(base + 2 * TILE_B, base + 3 * TILE_B, off1, vb1);        \
    } while (0)

    {
        float4 va0 = *(const float4*)pA0;
        float4 va1 = *(const float4*)pA1;
        float4 vb0 = *(const float4*)pB0;
        float4 vb1 = *(const float4*)pB1;
        FILL(0, va0, va1, vb0, vb1);
    }
    __syncthreads();

    const int NST = DD / 16;   // 64 stages
    for (int s = 0; s < NST; s++) {
        int buf = s & 1;
        float4 na0, na1, nb0, nb1;
        if (s + 1 < NST) {
            na0 = *(const float4*)(pA0 + (s + 1) * 16);
            na1 = *(const float4*)(pA1 + (s + 1) * 16);
            nb0 = *(const float4*)(pB0 + (s + 1) * 16);
            nb1 = *(const float4*)(pB1 + (s + 1) * 16);
        }

        uint32_t base = smb + buf * STAGE_B;
        // hoist all fragments: 12 ldmatrix per stage, 48 MMAs from registers
        uint32_t a0h[4], a1h[4], a0l[4], a1l[4];
        ldsm_x4(a0h, base + am0);
        ldsm_x4(a1h, base + am1);
        ldsm_x4(a0l, base + TILE_B + am0);
        ldsm_x4(a1l, base + TILE_B + am1);
#pragma unroll
        for (int nf = 0; nf < 4; nf++) {
            uint32_t bhf[4], blf[4];
            ldsm_x4(bhf, base + 2 * TILE_B + bn[nf]);
            ldsm_x4(blf, base + 3 * TILE_B + bn[nf]);
            // Ah*Bh
            mma_bf16(acc[0][2 * nf],     a0h, bhf[0], bhf[1]);
            mma_bf16(acc[0][2 * nf + 1], a0h, bhf[2], bhf[3]);
            mma_bf16(acc[1][2 * nf],     a1h, bhf[0], bhf[1]);
            mma_bf16(acc[1][2 * nf + 1], a1h, bhf[2], bhf[3]);
            // Ah*Bl
            mma_bf16(acc[0][2 * nf],     a0h, blf[0], blf[1]);
            mma_bf16(acc[0][2 * nf + 1], a0h, blf[2], blf[3]);
            mma_bf16(acc[1][2 * nf],     a1h, blf[0], blf[1]);
            mma_bf16(acc[1][2 * nf + 1], a1h, blf[2], blf[3]);
            // Al*Bh
            mma_bf16(acc[0][2 * nf],     a0l, bhf[0], bhf[1]);
            mma_bf16(acc[0][2 * nf + 1], a0l, bhf[2], bhf[3]);
            mma_bf16(acc[1][2 * nf],     a1l, bhf[0], bhf[1]);
            mma_bf16(acc[1][2 * nf + 1], a1l, bhf[2], bhf[3]);
        }

        if (s + 1 < NST) FILL(buf ^ 1, na0, na1, nb0, nb1);
        __syncthreads();
    }
#undef FILL

    const int grp = lane >> 2, qd = lane & 3;
#pragma unroll
    for (int mi = 0; mi < 2; mi++) {
#pragma unroll
        for (int half = 0; half < 2; half++) {
            int j = j0 + mw * 32 + mi * 16 + grp + half * 8;
            float bj = bias[j];
            float* dst = Ct + ((size_t)(b * DD + j)) * SS + s0 + nw * 64 + qd * 2;
#pragma unroll
            for (int ni = 0; ni < 8; ni++) {
                float2 v = make_float2(acc[mi][ni][half * 2 + 0] + bj,
                                       acc[mi][ni][half * 2 + 1] + bj);
                *(float2*)(dst + ni * 8) = v;
            }
        }
    }
}

// ---------------- kernel 2: packed forward FFT of (q + i*k), per (b,h,d) ----------------
__global__ void fft_qk_kernel() {
    int bhd = blockIdx.x;
    const float* qr = g_Qt + (size_t)bhd * SS;
    const float* kr = g_Kt + (size_t)bhd * SS;

    __shared__ float2 z[2048];
    __shared__ float2 tw[1024];

    int tid = threadIdx.x;
    for (int i = tid; i < 1024; i += 256) tw[i] = g_twf[i];
    for (int s = tid; s < 2048; s += 256) {
        int rs = __brev((unsigned)s) >> 21;
        z[rs] = make_float2(qr[s], kr[s]);
    }
    __syncthreads();

    float2 r[8];
    fft2048_hybrid(z, tw, r);
    // write back last-3-stage results (cross-thread access needed for unpack)
#pragma unroll
    for (int k = 0; k < 8; k++) z[tid + 256 * k] = r[k];
    __syncthreads();

    for (int f = tid; f < 2048; f += 256) {
        float2 Zf = z[f];
        float2 Zc = z[(2048 - f) & 2047];
        float Qr =  0.5f * (Zf.x + Zc.x);
        float Qi =  0.5f * (Zf.y - Zc.y);
        float Kr =  0.5f * (Zf.y + Zc.y);
        float Ki = -0.5f * (Zf.x - Zc.x);
        g_P[(size_t)bhd * SS + f] = make_float2(Qr * Kr + Qi * Ki, Qi * Kr - Qr * Ki);
    }
}

// ---------------- kernel 2b: reduce spectra over channel dim d ----------------
__global__ void reduce_kernel() {
    int bh = blockIdx.x;
    int f  = blockIdx.y * 256 + threadIdx.x;
    const float2* Pb = g_P + (size_t)bh * DH * SS + f;
    float sr = 0.0f, si = 0.0f;
#pragma unroll 8
    for (int d = 0; d < DH; d++) {
        float2 p = Pb[(size_t)d * SS];
        sr += p.x;
        si += p.y;
    }
    g_Ps[bh * SS + f] = make_float2(sr, si);
}

// ---------------- kernel 3: inverse FFT + top-k + softmax (per (b,h)) ----------------
__global__ void corr_topk_kernel() {
    int bh = blockIdx.x;

    __shared__ float2 z[2048];
    __shared__ float2 tw[1024];
    __shared__ unsigned long long key[2048];
    __shared__ float red[256];

    int tid = threadIdx.x;
    for (int i = tid; i < 1024; i += 256) tw[i] = g_twf[i];

    // load conj(Psum) bit-reversed (iFFT via conj trick)
    for (int f = tid; f < 2048; f += 256) {
        float2 p = g_Ps[bh * SS + f];
        int rf = __brev((unsigned)f) >> 21;
        z[rf] = make_float2(p.x, -p.y);
    }
    __syncthreads();

    float2 r[8];
    fft2048_hybrid(z, tw, r);
    // r[k] = Z[tid + 256k]; consume directly: mean_corr[t] = Re(Z[t]) / (2048*512)
#pragma unroll
    for (int k = 0; k < 8; k++) {
        int t = tid + 256 * k;
        float v = r[k].x * (1.0f / (2048.0f * 512.0f));
        key[t] = ((unsigned long long)fenc(v) << 32) | (unsigned)(2047 - t);
    }
    __syncthreads();

    // bitonic sort descending (== lax.top_k order: value desc, index asc on ties)
    for (int k = 2; k <= 2048; k <<= 1) {
        for (int j = k >> 1; j > 0; j >>= 1) {
            for (int t = tid; t < 2048; t += 256) {
                int ixj = t ^ j;
                if (ixj > t) {
                    unsigned long long A = key[t], Bv = key[ixj];
                    bool desc = ((t & k) == 0);
                    bool sw = desc ? (Bv > A) : (A > Bv);
                    if (sw) { key[t] = Bv; key[ixj] = A; }
                }
            }
            __syncthreads();
        }
    }

    float maxv = fdec((unsigned)(key[0] >> 32));
    float lsum = 0.0f;
    for (int k = tid; k < KTOP; k += 256) lsum += expf(fdec((unsigned)(key[k] >> 32)) - maxv);
    red[tid] = lsum;
    for (int off = 128; off > 0; off >>= 1) {
        __syncthreads();
        if (tid < off) red[tid] += red[tid + off];
    }
    __syncthreads();
    float total = red[0];

    for (int k = tid; k < KTOP; k += 256) {
        unsigned long long K = key[k];
        float v = fdec((unsigned)(K >> 32));
        int idx = 2047 - (int)(K & 0xFFFFFFFFull);
        g_wk[bh * 512 + k] = make_float2(expf(v - maxv) / total, (float)idx);
    }
}

// ---------------- kernel 3b: weighted gather  zv[bh][c] = sum_k w_k xv[b,idx_k,c] ----
__global__ void gather_kernel(const float* __restrict__ xv) {
    int bh = blockIdx.x;
    int b  = bh >> 4;
    int tid = threadIdx.x;
    __shared__ float2 ws[KTOP];
    for (int i = tid; i < KTOP; i += 256) ws[i] = g_wk[bh * 512 + i];
    __syncthreads();

    int c = blockIdx.y * 256 + tid;
    const float* xb = xv + (size_t)b * SS * DD + c;
    float acc = 0.0f;
#pragma unroll 4
    for (int k = 0; k < KTOP; k++) {
        float2 w = ws[k];
        acc += w.x * xb[(size_t)((int)w.y) * DD];
    }
    g_zv[bh * DD + c] = acc;
}

// ---------------- kernel 3c: attend  att[b][j] = sum_c zv[b,h(j)][c] wv[c][j] + bv ---
__global__ void attend_kernel(const float* __restrict__ wv, const float* __restrict__ bv) {
    int b = blockIdx.x, jc = blockIdx.y;
    int tid = threadIdx.x;
    int j = jc * 256 + tid;
    __shared__ float zs[4][1024];    // 4 heads' zv rows for this j-range
    int h0 = jc * 4;
    for (int i = tid; i < 4096; i += 256)
        zs[i >> 10][i & 1023] = g_zv[(b * HH + h0 + (i >> 10)) * DD + (i & 1023)];
    __syncthreads();

    int hl = (j >> 6) & 3;
    float acc = 0.0f;
#pragma unroll 4
    for (int c = 0; c < DD; c++)
        acc += zs[hl][c] * wv[(size_t)c * DD + j];
    g_att[b * DD + j] = acc + bv[j];
}

// ---------------- kernel 4: y[b] = attended[b] @ wo + bo ----------------
__global__ void proj_y_kernel(const float* __restrict__ wo, const float* __restrict__ bo) {
    int b = blockIdx.x;
    int j = threadIdx.x;
    __shared__ float av[DD];
    av[j] = g_att[b * DD + j];
    __syncthreads();
    float acc = 0.0f;
    for (int i = 0; i < DD; i++) acc += av[i] * wo[(size_t)i * DD + j];
    g_y[b * DD + j] = acc + bo[j];
}

// ---------------- kernel 5: broadcast across sequence ----------------
__global__ void bcast_kernel(float* __restrict__ out) {
    int idx = blockIdx.x * blockDim.x + threadIdx.x;
    int j4 = idx & 255;
    int bs = idx >> 8;
    int b  = bs >> 11;
    ((float4*)out)[idx] = ((const float4*)g_y)[b * 256 + j4];
}

// ---------------- launch ----------------
extern "C" void kernel_launch(void* const* d_in, const int* in_sizes, int n_in,
                              void* d_out, int out_size) {
    const float* xq = (const float*)d_in[0];
    const float* xk = (const float*)d_in[1];
    const float* xv = (const float*)d_in[2];
    const float* wq = (const float*)d_in[3];
    const float* bq = (const float*)d_in[4];
    const float* wk = (const float*)d_in[5];
    const float* bk = (const float*)d_in[6];
    const float* wv = (const float*)d_in[7];
    const float* bv = (const float*)d_in[8];
    const float* wo = (const float*)d_in[9];
    const float* bo = (const float*)d_in[10];
    float* out = (float*)d_out;

    float* wqt; cudaGetSymbolAddress((void**)&wqt, g_Wqt);
    float* wkt; cudaGetSymbolAddress((void**)&wkt, g_Wkt);
    float* qt;  cudaGetSymbolAddress((void**)&qt,  g_Qt);
    float* kt;  cudaGetSymbolAddress((void**)&kt,  g_Kt);

    tw_init_kernel<<<4, 256>>>();
    wtrans_kernel<<<dim3(32, 32), dim3(32, 8)>>>(wq, wqt);
    wtrans_kernel<<<dim3(32, 32), dim3(32, 8)>>>(wk, wkt);
    gemm_mma_kernel<<<dim3(DD / 128, SS / 128, BB), 256>>>(xq, wqt, bq, qt);
    gemm_mma_kernel<<<dim3(DD / 128, SS / 128, BB), 256>>>(xk, wkt, bk, kt);
    fft_qk_kernel<<<BB * DD, 256>>>();
    reduce_kernel<<<dim3(BB * HH, 8), 256>>>();
    corr_topk_kernel<<<BB * HH, 256>>>();
    gather_kernel<<<dim3(BB * HH, 4), 256>>>(xv);
    attend_kernel<<<dim3(BB, 4), 256>>>(wv, bv);
    proj_y_kernel<<<BB, DD>>>(wo, bo);
    bcast_kernel<<<(BB * SS * DD / 4) / 256, 256>>>(out);
}

// round 16
// speedup vs baseline: 1.7930x; 1.0268x over previous
#include <cuda_runtime.h>
#include <cuda_bf16.h>
#include <math.h>
#include <stdint.h>

// Problem constants
#define BB   4
#define SS   2048
#define DD   1024
#define HH   16
#define DH   64
#define KTOP 409        // max(S // 5, 1)

// ---------------- scratch (device globals; no allocation allowed) ----------------
__device__ float   g_Qt[(size_t)BB * DD * SS];   // Q transposed: [b*D + j][s]
__device__ float   g_Kt[(size_t)BB * DD * SS];   // K transposed
__device__ float2  g_P[(size_t)BB * DD * SS];    // spectrum product, REV-SLOT order
__device__ float2  g_Ps[64 * SS];                // d-reduced spectra, REV-SLOT order
__device__ float2  g_wk[64 * 512];               // (weight, index) per (b,h)
__device__ float   g_zv[64 * DD];                // weighted xv sums per (b,h)
__device__ float   g_att[BB * DD];
__device__ float   g_y[BB * DD];
__device__ float2  g_twf[1024];                  // exp(-2*pi*i*j/2048)

// bf16 hi/lo pre-split operands
__device__ __nv_bfloat16 g_Ahq[(size_t)DD * DD], g_Alq[(size_t)DD * DD];
__device__ __nv_bfloat16 g_Ahk[(size_t)DD * DD], g_Alk[(size_t)DD * DD];
__device__ __nv_bfloat16 g_Bhq[(size_t)BB * SS * DD], g_Blq[(size_t)BB * SS * DD];
__device__ __nv_bfloat16 g_Bhk[(size_t)BB * SS * DD], g_Blk[(size_t)BB * SS * DD];

// ---------------- PTX helpers (sm_80-compatible subset only) ----------------
__device__ __forceinline__ uint32_t smem_u32(const void* p) {
    uint32_t a;
    asm("{ .reg .u64 t; cvta.to.shared.u64 t, %1; cvt.u32.u64 %0, t; }" : "=r"(a) : "l"(p));
    return a;
}
__device__ __forceinline__ void ldsm_x4(uint32_t (&r)[4], uint32_t addr) {
    asm volatile("ldmatrix.sync.aligned.m8n8.x4.shared.b16 {%0,%1,%2,%3}, [%4];"
        : "=r"(r[0]), "=r"(r[1]), "=r"(r[2]), "=r"(r[3]) : "r"(addr));
}
__device__ __forceinline__ void mma_bf16(float (&c)[4], const uint32_t (&a)[4],
                                         uint32_t b0, uint32_t b1) {
    asm volatile(
        "mma.sync.aligned.m16n8k16.row.col.f32.bf16.bf16.f32 "
        "{%0,%1,%2,%3}, {%4,%5,%6,%7}, {%8,%9}, {%0,%1,%2,%3};"
        : "+f"(c[0]), "+f"(c[1]), "+f"(c[2]), "+f"(c[3])
        : "r"(a[0]), "r"(a[1]), "r"(a[2]), "r"(a[3]), "r"(b0), "r"(b1));
}
__device__ __forceinline__ void cp16(uint32_t dst, const void* src) {
    asm volatile("cp.async.cg.shared.global [%0], [%1], 16;" :: "r"(dst), "l"(src));
}
#define CP_COMMIT() asm volatile("cp.async.commit_group;" ::: "memory")
#define CP_WAIT2()  asm volatile("cp.async.wait_group 2;" ::: "memory")

// ---------------- FFT helpers ----------------
__device__ __forceinline__ void bflyDIT(float2& u, float2& v, float2 w) {
    float tr = w.x * v.x - w.y * v.y;
    float ti = w.x * v.y + w.y * v.x;
    float2 t = make_float2(u.x - tr, u.y - ti);
    u = make_float2(u.x + tr, u.y + ti);
    v = t;
}
__device__ __forceinline__ void bflyDIF(float2& u, float2& v, float2 w) {
    float2 t = make_float2(u.x - v.x, u.y - v.y);
    u = make_float2(u.x + v.x, u.y + v.y);
    v = make_float2(t.x * w.x - t.y * w.y, t.x * w.y + t.y * w.x);
}

// DIT FFT, bit-reversed input in z, natural output.
// Stages half=1..128 in smem; last 3 (256/512/1024) in regs: r[k] = Z[tid+256k].
__device__ void fft2048_dit_hybrid(float2* z, const float2* tw, float2 (&r)[8]) {
    int tid = threadIdx.x;
    for (int half = 1; half < 256; half <<= 1) {
        int step = 1024 / half;
        for (int jj = tid; jj < 1024; jj += 256) {
            int p  = jj & (half - 1);
            int i0 = ((jj ^ p) << 1) | p;
            int i1 = i0 + half;
            float2 w = tw[p * step];
            float2 v = z[i1];
            float tr = w.x * v.x - w.y * v.y;
            float ti = w.x * v.y + w.y * v.x;
            float2 u = z[i0];
            z[i0] = make_float2(u.x + tr, u.y + ti);
            z[i1] = make_float2(u.x - tr, u.y - ti);
        }
        __syncthreads();
    }
#pragma unroll
    for (int k = 0; k < 8; k++) r[k] = z[tid + 256 * k];
    float2 w4 = tw[4 * tid];
    bflyDIT(r[0], r[1], w4); bflyDIT(r[2], r[3], w4);
    bflyDIT(r[4], r[5], w4); bflyDIT(r[6], r[7], w4);
    float2 w20 = tw[2 * tid], w21 = tw[2 * tid + 512];
    bflyDIT(r[0], r[2], w20); bflyDIT(r[1], r[3], w21);
    bflyDIT(r[4], r[6], w20); bflyDIT(r[5], r[7], w21);
    bflyDIT(r[0], r[4], tw[tid]);
    bflyDIT(r[1], r[5], tw[tid + 256]);
    bflyDIT(r[2], r[6], tw[tid + 512]);
    bflyDIT(r[3], r[7], tw[tid + 768]);
}

__device__ __forceinline__ unsigned int fenc(float v) {
    unsigned int u = __float_as_uint(v);
    return (u & 0x80000000u) ? ~u : (u | 0x80000000u);
}
__device__ __forceinline__ float fdec(unsigned int e) {
    unsigned int u = (e & 0x80000000u) ? (e & 0x7FFFFFFFu) : ~e;
    return __uint_as_float(u);
}

// ---------------- kernel 0: twiddle table ----------------
__global__ void tw_init_kernel() {
    int i = blockIdx.x * blockDim.x + threadIdx.x;
    if (i < 1024) {
        double ang = -2.0 * 3.14159265358979323846 * (double)i / 2048.0;
        g_twf[i] = make_float2((float)cos(ang), (float)sin(ang));
    }
}

// ---------------- kernel 0b: W transpose + bf16 hi/lo split ----------------
// Ah/Al[j][c] = split(W[c][j])
__global__ void splitw_kernel(const float* __restrict__ W,
                              __nv_bfloat16* __restrict__ Ah,
                              __nv_bfloat16* __restrict__ Al) {
    __shared__ float t[32][33];
    int bx = blockIdx.x * 32, by = blockIdx.y * 32;
    int x = threadIdx.x, y = threadIdx.y;  // block (32,8)
#pragma unroll
    for (int i = 0; i < 32; i += 8)
        t[y + i][x] = W[(size_t)(by + y + i) * DD + bx + x];
    __syncthreads();
#pragma unroll
    for (int i = 0; i < 32; i += 8) {
        float v = t[x][y + i];
        __nv_bfloat16 h = __float2bfloat16(v);
        __nv_bfloat16 l = __float2bfloat16(v - __bfloat162float(h));
        Ah[(size_t)(bx + y + i) * DD + by + x] = h;
        Al[(size_t)(bx + y + i) * DD + by + x] = l;
    }
}

// ---------------- kernel 0c: X bf16 hi/lo split (elementwise) ----------------
__global__ void splitx_kernel(const float* __restrict__ X,
                              __nv_bfloat16* __restrict__ H,
                              __nv_bfloat16* __restrict__ L) {
    size_t i = ((size_t)blockIdx.x * 256 + threadIdx.x) * 4;
    float4 v = *(const float4*)&X[i];
    __nv_bfloat162 h0 = __float22bfloat162_rn(make_float2(v.x, v.y));
    __nv_bfloat162 h1 = __float22bfloat162_rn(make_float2(v.z, v.w));
    float2 f0 = __bfloat1622float2(h0), f1 = __bfloat1622float2(h1);
    __nv_bfloat162 l0 = __float22bfloat162_rn(make_float2(v.x - f0.x, v.y - f0.y));
    __nv_bfloat162 l1 = __float22bfloat162_rn(make_float2(v.z - f1.x, v.w - f1.y));
    uint2 Hv, Lv;
    Hv.x = *(uint32_t*)&h0; Hv.y = *(uint32_t*)&h1;
    Lv.x = *(uint32_t*)&l0; Lv.y = *(uint32_t*)&l1;
    *(uint2*)&H[i] = Hv;
    *(uint2*)&L[i] = Lv;
}

// ---------------- kernel 1: bf16x3 tensor-core GEMM, cp.async 4-stage pipeline ----
// Ct[(b*D + j)*S + s] = sum_c A[j][c] * B[(b*S+s)][c] + bias[j]
// Both GEMMs (q: which=0, k: which=1) in one launch; which = blockIdx.z >> 2.
#define ROWB    48
#define TILE_B  (128 * ROWB)          // 6144 B
#define STAGE_B (4 * TILE_B)          // 24576 B (Ah, Al, Bh, Bl)
#define PIPE    4
#define GSMEM   (PIPE * STAGE_B)      // 98304 B

__global__ __launch_bounds__(256)
void gemm_mma_kernel(const float* __restrict__ bq, const float* __restrict__ bk) {
    extern __shared__ __align__(16) char sm[];

    const int tid  = threadIdx.x;
    const int lane = tid & 31, wid = tid >> 5;
    const int mw = wid & 3, nw = wid >> 2;           // 4 x 2 warp grid
    const int which = blockIdx.z >> 2;
    const int b  = blockIdx.z & 3;
    const int j0 = blockIdx.x * 128;
    const int s0 = blockIdx.y * 128;

    const __nv_bfloat16* Ah = which ? g_Ahk : g_Ahq;
    const __nv_bfloat16* Al = which ? g_Alk : g_Alq;
    const __nv_bfloat16* Bh = which ? g_Bhk : g_Bhq;
    const __nv_bfloat16* Bl = which ? g_Blk : g_Blq;
    const float* bias = which ? bk : bq;
    float* Ct = which ? g_Kt : g_Qt;

    // ---- cp.async source/dst mapping: thread -> (row, 16B-half), one chunk per tile
    const int row2  = tid >> 1;
    const int halfe = (tid & 1) * 8;                 // element offset within row
    const uint32_t dsto = row2 * ROWB + (tid & 1) * 16;
    const __nv_bfloat16* sAh = Ah + (size_t)(j0 + row2) * DD + halfe;
    const __nv_bfloat16* sAl = Al + (size_t)(j0 + row2) * DD + halfe;
    const __nv_bfloat16* sBh = Bh + (size_t)(b * SS + s0 + row2) * DD + halfe;
    const __nv_bfloat16* sBl = Bl + (size_t)(b * SS + s0 + row2) * DD + halfe;

    uint32_t smb = smem_u32(sm);

    // ---- ldmatrix lane addressing ----
    const int aoff = (lane & 15) * ROWB + (lane >> 4) * 16;
    const int am0 = (mw * 32 +  0) * ROWB + aoff;
    const int am1 = (mw * 32 + 16) * ROWB + aoff;
    const int nloc = (lane & 7) + ((lane >> 4) << 3);
    const int boff = ((lane >> 3) & 1) * 16;
    int bn[4];
#pragma unroll
    for (int nf = 0; nf < 4; nf++)
        bn[nf] = (nw * 64 + nf * 16 + nloc) * ROWB + boff;

    float acc[2][8][4];
#pragma unroll
    for (int mi = 0; mi < 2; mi++)
#pragma unroll
        for (int ni = 0; ni < 8; ni++)
#pragma unroll
            for (int q = 0; q < 4; q++) acc[mi][ni][q] = 0.0f;

#define ISSUE(st) do {                                                  \
        uint32_t d = smb + ((st) & (PIPE - 1)) * STAGE_B + dsto;        \
        int kt = (st) * 16;                                             \
        cp16(d,              sAh + kt);                                 \
        cp16(d + TILE_B,     sAl + kt);                                 \
        cp16(d + 2 * TILE_B, sBh + kt);                                 \
        cp16(d + 3 * TILE_B, sBl + kt);                                 \
        CP_COMMIT();                                                    \
    } while (0)

    ISSUE(0); ISSUE(1); ISSUE(2);

    const int NST = DD / 16;   // 64 stages
    for (int s = 0; s < NST; s++) {
        CP_WAIT2();
        __syncthreads();
        if (s + 3 < NST) ISSUE(s + 3);

        uint32_t base = smb + (s & (PIPE - 1)) * STAGE_B;
        uint32_t a0h[4], a1h[4], a0l[4], a1l[4];
        ldsm_x4(a0h, base + am0);
        ldsm_x4(a1h, base + am1);
        ldsm_x4(a0l, base + TILE_B + am0);
        ldsm_x4(a1l, base + TILE_B + am1);
#pragma unroll
        for (int nf = 0; nf < 4; nf++) {
            uint32_t bhf[4], blf[4];
            ldsm_x4(bhf, base + 2 * TILE_B + bn[nf]);
            ldsm_x4(blf, base + 3 * TILE_B + bn[nf]);
            mma_bf16(acc[0][2 * nf],     a0h, bhf[0], bhf[1]);
            mma_bf16(acc[0][2 * nf + 1], a0h, bhf[2], bhf[3]);
            mma_bf16(acc[1][2 * nf],     a1h, bhf[0], bhf[1]);
            mma_bf16(acc[1][2 * nf + 1], a1h, bhf[2], bhf[3]);
            mma_bf16(acc[0][2 * nf],     a0h, blf[0], blf[1]);
            mma_bf16(acc[0][2 * nf + 1], a0h, blf[2], blf[3]);
            mma_bf16(acc[1][2 * nf],     a1h, blf[0], blf[1]);
            mma_bf16(acc[1][2 * nf + 1], a1h, blf[2], blf[3]);
            mma_bf16(acc[0][2 * nf],     a0l, bhf[0], bhf[1]);
            mma_bf16(acc[0][2 * nf + 1], a0l, bhf[2], bhf[3]);
            mma_bf16(acc[1][2 * nf],     a1l, bhf[0], bhf[1]);
            mma_bf16(acc[1][2 * nf + 1], a1l, bhf[2], bhf[3]);
        }
    }
#undef ISSUE

    const int grp = lane >> 2, qd = lane & 3;
#pragma unroll
    for (int mi = 0; mi < 2; mi++) {
#pragma unroll
        for (int half = 0; half < 2; half++) {
            int j = j0 + mw * 32 + mi * 16 + grp + half * 8;
            float bj = bias[j];
            float* dst = Ct + ((size_t)(b * DD + j)) * SS + s0 + nw * 64 + qd * 2;
#pragma unroll
            for (int ni = 0; ni < 8; ni++) {
                float2 v = make_float2(acc[mi][ni][half * 2 + 0] + bj,
                                       acc[mi][ni][half * 2 + 1] + bj);
                *(float2*)(dst + ni * 8) = v;
            }
        }
    }
}

// ---------------- kernel 2: packed forward DIF FFT of (q + i*k) ----------------
// Natural-order input (no scatter!), bit-reversed output slots; unpack done in the
// rev domain; g_P stored in rev-slot order.
__global__ void fft_qk_kernel() {
    int bhd = blockIdx.x;
    const float* qr = g_Qt + (size_t)bhd * SS;
    const float* kr = g_Kt + (size_t)bhd * SS;

    __shared__ float2 z[2048];
    __shared__ float2 tw[1024];

    int tid = threadIdx.x;
    for (int i = tid; i < 1024; i += 256) tw[i] = g_twf[i];

    float2 r[8];
#pragma unroll
    for (int k = 0; k < 8; k++) {
        int s = tid + 256 * k;
        r[k] = make_float2(qr[s], kr[s]);
    }
    __syncthreads();   // tw visible

    // DIF reg stages: half = 1024, 512, 256
#pragma unroll
    for (int k = 0; k < 4; k++) bflyDIF(r[k], r[k + 4], tw[tid + 256 * k]);
    {
        float2 w0 = tw[2 * tid], w1 = tw[2 * tid + 512];
        bflyDIF(r[0], r[2], w0); bflyDIF(r[1], r[3], w1);
        bflyDIF(r[4], r[6], w0); bflyDIF(r[5], r[7], w1);
    }
    {
        float2 w = tw[4 * tid];
        bflyDIF(r[0], r[1], w); bflyDIF(r[2], r[3], w);
        bflyDIF(r[4], r[5], w); bflyDIF(r[6], r[7], w);
    }
#pragma unroll
    for (int k = 0; k < 8; k++) z[tid + 256 * k] = r[k];
    __syncthreads();

    // DIF smem stages: half = 128 .. 1
    for (int half = 128; half >= 1; half >>= 1) {
        int step = 1024 / half;
        for (int jj = tid; jj < 1024; jj += 256) {
            int p  = jj & (half - 1);
            int i0 = ((jj ^ p) << 1) | p;
            int i1 = i0 + half;
            float2 w = tw[p * step];
            float2 u = z[i0], v = z[i1];
            float2 t = make_float2(u.x - v.x, u.y - v.y);
            z[i0] = make_float2(u.x + v.x, u.y + v.y);
            z[i1] = make_float2(t.x * w.x - t.y * w.y, t.x * w.y + t.y * w.x);
        }
        __syncthreads();
    }

    // Unpack in rev domain: slot i holds Z[brev(i)].  P = Q * conj(K).
#pragma unroll
    for (int k = 0; k < 8; k++) {
        int i = tid + 256 * k;
        int f  = __brev((unsigned)i) >> 21;
        int fp = (2048 - f) & 2047;
        int jp = __brev((unsigned)fp) >> 21;
        float2 Zf = z[i];
        float2 Zc = z[jp];
        float Qr =  0.5f * (Zf.x + Zc.x);
        float Qi =  0.5f * (Zf.y - Zc.y);
        float Kr =  0.5f * (Zf.y + Zc.y);
        float Ki = -0.5f * (Zf.x - Zc.x);
        g_P[(size_t)bhd * SS + i] = make_float2(Qr * Kr + Qi * Ki, Qi * Kr - Qr * Ki);
    }
}

// ---------------- kernel 2b: reduce spectra over channel dim d (slot-pointwise) ----
__global__ void reduce_kernel() {
    int bh = blockIdx.x;
    int f  = blockIdx.y * 256 + threadIdx.x;
    const float2* Pb = g_P + (size_t)bh * DH * SS + f;
    float sr = 0.0f, si = 0.0f;
#pragma unroll 8
    for (int d = 0; d < DH; d++) {
        float2 p = Pb[(size_t)d * SS];
        sr += p.x;
        si += p.y;
    }
    g_Ps[bh * SS + f] = make_float2(sr, si);
}

// ---------------- kernel 3: inverse DIT FFT + top-k + softmax ----------------
// g_Ps is in rev-slot order == exactly the bit-reversed input DIT wants. No scatter.
__global__ void corr_topk_kernel() {
    int bh = blockIdx.x;

    __shared__ float2 z[2048];
    __shared__ float2 tw[1024];
    __shared__ unsigned long long key[2048];
    __shared__ float red[256];

    int tid = threadIdx.x;
    for (int i = tid; i < 1024; i += 256) tw[i] = g_twf[i];
    for (int i = tid; i < 2048; i += 256) {
        float2 p = g_Ps[bh * SS + i];
        z[i] = make_float2(p.x, -p.y);   // conj trick for inverse
    }
    __syncthreads();

    float2 r[8];
    fft2048_dit_hybrid(z, tw, r);
    // r[k] = Z[t], t = tid + 256k (natural order); mean_corr[t] = Re/(2048*512)
#pragma unroll
    for (int k = 0; k < 8; k++) {
        int t = tid + 256 * k;
        float v = r[k].x * (1.0f / (2048.0f * 512.0f));
        key[t] = ((unsigned long long)fenc(v) << 32) | (unsigned)(2047 - t);
    }
    __syncthreads();

    // bitonic sort descending (== lax.top_k order: value desc, index asc on ties)
    for (int k = 2; k <= 2048; k <<= 1) {
        for (int j = k >> 1; j > 0; j >>= 1) {
            for (int t = tid; t < 2048; t += 256) {
                int ixj = t ^ j;
                if (ixj > t) {
                    unsigned long long A = key[t], Bv = key[ixj];
                    bool desc = ((t & k) == 0);
                    bool sw = desc ? (Bv > A) : (A > Bv);
                    if (sw) { key[t] = Bv; key[ixj] = A; }
                }
            }
            __syncthreads();
        }
    }

    float maxv = fdec((unsigned)(key[0] >> 32));
    float lsum = 0.0f;
    for (int k = tid; k < KTOP; k += 256) lsum += expf(fdec((unsigned)(key[k] >> 32)) - maxv);
    red[tid] = lsum;
    for (int off = 128; off > 0; off >>= 1) {
        __syncthreads();
        if (tid < off) red[tid] += red[tid + off];
    }
    __syncthreads();
    float total = red[0];

    for (int k = tid; k < KTOP; k += 256) {
        unsigned long long K = key[k];
        float v = fdec((unsigned)(K >> 32));
        int idx = 2047 - (int)(K & 0xFFFFFFFFull);
        g_wk[bh * 512 + k] = make_float2(expf(v - maxv) / total, (float)idx);
    }
}

// ---------------- kernel 3b: weighted gather ----------------
__global__ void gather_kernel(const float* __restrict__ xv) {
    int bh = blockIdx.x;
    int b  = bh >> 4;
    int tid = threadIdx.x;
    __shared__ float2 ws[KTOP];
    for (int i = tid; i < KTOP; i += 256) ws[i] = g_wk[bh * 512 + i];
    __syncthreads();

    int c = blockIdx.y * 256 + tid;
    const float* xb = xv + (size_t)b * SS * DD + c;
    float acc = 0.0f;
#pragma unroll 4
    for (int k = 0; k < KTOP; k++) {
        float2 w = ws[k];
        acc += w.x * xb[(size_t)((int)w.y) * DD];
    }
    g_zv[bh * DD + c] = acc;
}

// ---------------- kernel 3c: attend ----------------
__global__ void attend_kernel(const float* __restrict__ wv, const float* __restrict__ bv) {
    int b = blockIdx.x, jc = blockIdx.y;
    int tid = threadIdx.x;
    int j = jc * 256 + tid;
    __shared__ float zs[4][1024];
    int h0 = jc * 4;
    for (int i = tid; i < 4096; i += 256)
        zs[i >> 10][i & 1023] = g_zv[(b * HH + h0 + (i >> 10)) * DD + (i & 1023)];
    __syncthreads();

    int hl = (j >> 6) & 3;
    float acc = 0.0f;
#pragma unroll 4
    for (int c = 0; c < DD; c++)
        acc += zs[hl][c] * wv[(size_t)c * DD + j];
    g_att[b * DD + j] = acc + bv[j];
}

// ---------------- kernel 4: y[b] = attended[b] @ wo + bo ----------------
__global__ void proj_y_kernel(const float* __restrict__ wo, const float* __restrict__ bo) {
    int b = blockIdx.x;
    int j = threadIdx.x;
    __shared__ float av[DD];
    av[j] = g_att[b * DD + j];
    __syncthreads();
    float acc = 0.0f;
    for (int i = 0; i < DD; i++) acc += av[i] * wo[(size_t)i * DD + j];
    g_y[b * DD + j] = acc + bo[j];
}

// ---------------- kernel 5: broadcast across sequence ----------------
__global__ void bcast_kernel(float* __restrict__ out) {
    int idx = blockIdx.x * blockDim.x + threadIdx.x;
    int j4 = idx & 255;
    int bs = idx >> 8;
    int b  = bs >> 11;
    ((float4*)out)[idx] = ((const float4*)g_y)[b * 256 + j4];
}

// ---------------- launch ----------------
extern "C" void kernel_launch(void* const* d_in, const int* in_sizes, int n_in,
                              void* d_out, int out_size) {
    const float* xq = (const float*)d_in[0];
    const float* xk = (const float*)d_in[1];
    const float* xv = (const float*)d_in[2];
    const float* wq = (const float*)d_in[3];
    const float* bq = (const float*)d_in[4];
    const float* wk = (const float*)d_in[5];
    const float* bk = (const float*)d_in[6];
    const float* wv = (const float*)d_in[7];
    const float* bv = (const float*)d_in[8];
    const float* wo = (const float*)d_in[9];
    const float* bo = (const float*)d_in[10];
    float* out = (float*)d_out;

    __nv_bfloat16 *ahq, *alq, *ahk, *alk, *bhq, *blq, *bhk, *blk;
    cudaGetSymbolAddress((void**)&ahq, g_Ahq);
    cudaGetSymbolAddress((void**)&alq, g_Alq);
    cudaGetSymbolAddress((void**)&ahk, g_Ahk);
    cudaGetSymbolAddress((void**)&alk, g_Alk);
    cudaGetSymbolAddress((void**)&bhq, g_Bhq);
    cudaGetSymbolAddress((void**)&blq, g_Blq);
    cudaGetSymbolAddress((void**)&bhk, g_Bhk);
    cudaGetSymbolAddress((void**)&blk, g_Blk);

    cudaFuncSetAttribute(gemm_mma_kernel, cudaFuncAttributeMaxDynamicSharedMemorySize, GSMEM);

    tw_init_kernel<<<4, 256>>>();
    splitw_kernel<<<dim3(32, 32), dim3(32, 8)>>>(wq, ahq, alq);
    splitw_kernel<<<dim3(32, 32), dim3(32, 8)>>>(wk, ahk, alk);
    splitx_kernel<<<(BB * SS * DD / 4) / 256, 256>>>(xq, bhq, blq);
    splitx_kernel<<<(BB * SS * DD / 4) / 256, 256>>>(xk, bhk, blk);
    gemm_mma_kernel<<<dim3(DD / 128, SS / 128, BB * 2), 256, GSMEM>>>(bq, bk);
    fft_qk_kernel<<<BB * DD, 256>>>();
    reduce_kernel<<<dim3(BB * HH, 8), 256>>>();
    corr_topk_kernel<<<BB * HH, 256>>>();
    gather_kernel<<<dim3(BB * HH, 4), 256>>>(xv);
    attend_kernel<<<dim3(BB, 4), 256>>>(wv, bv);
    proj_y_kernel<<<BB, DD>>>(wo, bo);
    bcast_kernel<<<(BB * SS * DD / 4) / 256, 256>>>(out);
}